// round 15
// baseline (speedup 1.0000x reference)
#include <cuda_runtime.h>
#include <cuda_bf16.h>

#define TT 512
#define BB 32
#define VV 8000
#define LL 100
#define SS (2*LL+1)   // 201
#define NEGF (-1e30f)
#define LOG2E 1.4426950408889634f
#define LN2   0.6931471805599453f

#define SWARPS 9      // scan warps per sample
#define OWN   24      // owned states per warp (lanes 8..31)
#define MIR    8      // mirror lanes (0..7) = prev warp's top 8 states
#define NQUAD 127     // quads: quad q covers t = 1+4q .. 4+4q (t up to 508)

#define NSCAN BB              // 32 consumer blocks
#define NPROD (TT*BB)         // 16384 producer blocks (one row each)
#define NBLK  (NSCAN + NPROD)
#define NTHR  (32*SWARPS)     // 288 threads everywhere

// Scratch (allocation-free rule: __device__ globals; zero-initialized)
__device__ float g_lp[TT*BB*SS];      // log2-domain emissions (27 MB)
__device__ int   g_flags[TT*BB];      // row-ready flags (== epoch when ready)
__device__ int   g_epoch;

__device__ __forceinline__ float ex2f(float x) {
    float r; asm("ex2.approx.ftz.f32 %0, %1;" : "=f"(r) : "f"(x)); return r;
}
__device__ __forceinline__ float lg2f(float x) {
    float r; asm("lg2.approx.ftz.f32 %0, %1;" : "=f"(r) : "f"(x)); return r;
}

// ---------------------------------------------------------------------------
__global__ void init_kernel(float* __restrict__ out) {
    g_epoch = g_epoch + 1;
    out[0] = 0.f;
}

// ---------------------------------------------------------------------------
// Fused kernel.
//   blocks [0,32):   quad-scan consumers (wave-1 resident; 1-thread volatile
//                    polls with nanosleep; 8-step register prefetch tolerates
//                    DRAM-latency reads if the frontier lags)
//   blocks [32, +16384): producers, one (t,b) row each, t-major order.
// ---------------------------------------------------------------------------
__global__ __launch_bounds__(NTHR) void fused_kernel(const float* __restrict__ acts,
                                                     const int* __restrict__ targets,
                                                     const int* __restrict__ act_lens,
                                                     const int* __restrict__ label_lens,
                                                     float* __restrict__ out) {
    const int epoch = g_epoch;
    const int tid = threadIdx.x;
    volatile int* vflags = g_flags;

    if (blockIdx.x >= NSCAN) {
        // ================= PRODUCER: one row per block =================
        const int row = blockIdx.x - NSCAN;           // t*BB + b
        const int b   = row % BB;
        const float* __restrict__ rowp = acts + (size_t)row * VV;
        const float4* __restrict__ p = (const float4*)rowp;

        float s = 0.f;
        #pragma unroll 4
        for (int i = tid; i < VV/4; i += NTHR) {
            float4 v = p[i];
            s += ex2f(v.x * LOG2E) + ex2f(v.y * LOG2E)
               + ex2f(v.z * LOG2E) + ex2f(v.w * LOG2E);
        }
        #pragma unroll
        for (int off = 16; off; off >>= 1)
            s += __shfl_xor_sync(0xffffffffu, s, off);

        __shared__ float sv[SWARPS];
        __shared__ float sLogZ2;
        int w = tid >> 5;
        if ((tid & 31) == 0) sv[w] = s;
        __syncthreads();
        if (tid == 0) {
            float Sv = sv[0];
            #pragma unroll
            for (int i = 1; i < SWARPS; i++) Sv += sv[i];
            sLogZ2 = lg2f(Sv);
        }
        __syncthreads();

        if (tid < SS) {
            int lab = (tid & 1) ? __ldg(&targets[b*LL + (tid >> 1)]) : 0;
            g_lp[(size_t)row * SS + tid] = fmaf(rowp[lab], LOG2E, -sLogZ2);
        }
        __syncthreads();
        if (tid == 0) {
            __threadfence();                          // publish g_lp row
            vflags[row] = epoch;                      // release flag
        }
    } else {
        // ================= SCAN (consumer): quad scan =================
        const int b   = blockIdx.x;
        const int w   = tid >> 5;
        const int l   = tid & 31;
        const int s   = OWN * w + l - MIR;         // state id (mirrors for l<8)
        const bool live = (s >= 0 && s < SS);
        const bool owned = (l >= MIR) && live;
        const int alen = act_lens[b];

        __shared__ float bnd[2][SWARPS*MIR];
        __shared__ float fin[SS];

        bool cs = false;
        if (live && (s & 1)) {
            int cl = targets[b*LL + (s >> 1)];
            int pl = (s >= 3) ? targets[b*LL + ((s - 2) >> 1)] : -1;
            cs = (cl != 0) && (cl != pl);
        }

        auto step = [&](float av, float lp, int t) -> float {
            float x2 = __shfl_up_sync(0xffffffffu, av, 1);
            float x3 = __shfl_up_sync(0xffffffffu, av, 2);
            float x3e = cs ? x3 : NEGF;
            float m = fmaxf(av, fmaxf(x2, x3e));
            float r = ex2f(av - m) + ex2f(x2 - m) + ex2f(x3e - m);
            float nv = m + lg2f(r) + lp;
            nv = (t < alen) ? nv : av;
            return live ? nv : NEGF;
        };

        // ---- wait for rows 0..8 (alpha0 + first prefetch group)
        if (tid == 0) {
            #pragma unroll
            for (int t = 0; t <= 8; t++)
                while (vflags[t*BB + b] != epoch) __nanosleep(64);
            __threadfence();                          // acquire
        }
        __syncthreads();

        // alpha[0]
        float a = NEGF;
        if (live && s <= 1) a = g_lp[(size_t)b * SS + s];

        // lp prefetch: 2 quads (8 steps), compile-time slots
        float lqA[8], lqB[8];
        #pragma unroll
        for (int j = 0; j < 8; j++) {
            int t = 1 + j;
            lqA[j] = live ? g_lp[(size_t)(t*BB + b)*SS + s] : 0.f;
        }
        __syncthreads();

        for (int q0 = 0; q0 < NQUAD; q0 += 2) {
            // poll flags for next group's rows: t = 4*q0+9 .. 4*q0+16 (<=508)
            if (tid == 0) {
                #pragma unroll
                for (int jj = 0; jj < 8; jj++) {
                    int tn = 4*q0 + 9 + jj;
                    if (tn <= 508)
                        while (vflags[tn*BB + b] != epoch) __nanosleep(64);
                }
                __threadfence();                      // acquire
            }
            __syncthreads();

            // prefetch next group (compile-time slot index)
            #pragma unroll
            for (int j = 0; j < 8; j++) {
                int t = 1 + 4*(q0 + 2) + j;
                bool ok = live && (t <= 508);
                lqB[j] = ok ? g_lp[(size_t)(t*BB + b)*SS + s] : 0.f;
            }
            #pragma unroll
            for (int jq = 0; jq < 2; jq++) {
                const int q = q0 + jq;
                if (q >= NQUAD) break;                // uniform across block
                const int t = 1 + 4*q;

                float v1 = step(a,  lqA[4*jq + 0], t);
                float v2 = step(v1, lqA[4*jq + 1], t + 1);
                float v3 = step(v2, lqA[4*jq + 2], t + 2);
                float v4 = step(v3, lqA[4*jq + 3], t + 3);

                if (l >= 32 - MIR) bnd[jq][w*MIR + (l - (32 - MIR))] = v4;
                __syncthreads();
                if (l < MIR) a = (w > 0) ? bnd[jq][(w - 1)*MIR + l] : NEGF;
                else         a = v4;
            }
            #pragma unroll
            for (int j = 0; j < 8; j++) lqA[j] = lqB[j];
        }

        // ---- tail: t = 509, 510, 511 (poll, then one step per barrier)
        if (tid == 0) {
            #pragma unroll
            for (int t = 509; t <= 511; t++)
                while (vflags[t*BB + b] != epoch) __nanosleep(64);
            __threadfence();
        }
        __syncthreads();
        {
            float ltl0 = live ? g_lp[(size_t)(509*BB + b)*SS + s] : 0.f;
            float ltl1 = live ? g_lp[(size_t)(510*BB + b)*SS + s] : 0.f;
            float ltl2 = live ? g_lp[(size_t)(511*BB + b)*SS + s] : 0.f;

            float d = step(a, ltl0, 509);
            if (l >= 32 - MIR) bnd[1][w*MIR + (l - (32 - MIR))] = d;
            __syncthreads();
            a = (l < MIR) ? ((w > 0) ? bnd[1][(w - 1)*MIR + l] : NEGF) : d;

            d = step(a, ltl1, 510);
            if (l >= 32 - MIR) bnd[0][w*MIR + (l - (32 - MIR))] = d;
            __syncthreads();
            a = (l < MIR) ? ((w > 0) ? bnd[0][(w - 1)*MIR + l] : NEGF) : d;

            a = step(a, ltl2, 511);
        }

        if (owned) fin[s] = a;
        __syncthreads();
        if (tid == 0) {
            int sl = 2 * label_lens[b];
            float x = fin[sl], y = fin[sl - 1];
            float m = fmaxf(x, y);
            float ll2 = m + lg2f(ex2f(x - m) + ex2f(y - m));   // log2 domain
            atomicAdd(out, -ll2 * (LN2 / (float)BB));
        }
    }
}

// ---------------------------------------------------------------------------
extern "C" void kernel_launch(void* const* d_in, const int* in_sizes, int n_in,
                              void* d_out, int out_size) {
    const float* acts       = (const float*)d_in[0];
    const int*   targets    = (const int*)d_in[1];
    const int*   act_lens   = (const int*)d_in[2];
    const int*   label_lens = (const int*)d_in[3];
    float* out = (float*)d_out;

    init_kernel<<<1, 1>>>(out);
    fused_kernel<<<NBLK, NTHR>>>(acts, targets, act_lens, label_lens, out);
}

// round 16
// speedup vs baseline: 2.2505x; 2.2505x over previous
#include <cuda_runtime.h>
#include <cuda_bf16.h>

#define TT 512
#define BB 32
#define VV 8000
#define LL 100
#define SS (2*LL+1)   // 201
#define NEGF (-1e30f)
#define LOG2E 1.4426950408889634f
#define LN2   0.6931471805599453f

#define SWARPS 9      // scan warps per block
#define OWN   24      // owned states per warp
#define MIR    8      // mirror lanes
#define NQF   63      // forward quads: t = 1+4q .. 4+4q, q=0..62 (t<=252), tail 253..255
#define NQB   63      // backward quads: t = 510-4q .. 507-4q (t>=259), tail 258..255

// Scratch (allocation-free rule: __device__ globals)
__device__ float g_lp[TT*BB*SS];      // log2-domain emissions (27 MB)
__device__ float g_fa[BB*SS];         // alpha[255]
__device__ float g_fb[BB*SS];         // beta'[255]

__device__ __forceinline__ float ex2f(float x) {
    float r; asm("ex2.approx.ftz.f32 %0, %1;" : "=f"(r) : "f"(x)); return r;
}
__device__ __forceinline__ float lg2f(float x) {
    float r; asm("lg2.approx.ftz.f32 %0, %1;" : "=f"(r) : "f"(x)); return r;
}

// ---------------------------------------------------------------------------
// K1: logZ2 = lg2(sum exp2(x*log2e)) over V, then gather lp_ext (log2).
//     One block per (t,b) row.  (measured: ~86 us, 78% of HBM spec)
// ---------------------------------------------------------------------------
__global__ __launch_bounds__(256) void logz_gather_kernel(const float* __restrict__ acts,
                                                          const int* __restrict__ targets,
                                                          float* __restrict__ out) {
    const int row = blockIdx.x;                    // t*BB + b
    const int b   = row % BB;
    const float* __restrict__ rowp = acts + (size_t)row * VV;
    const float4* __restrict__ p = (const float4*)rowp;
    const int tid = threadIdx.x;

    if (row == 0 && tid == 0) out[0] = 0.f;

    float s = 0.f;
    #pragma unroll 4
    for (int i = tid; i < VV/4; i += 256) {
        float4 v = p[i];
        s += ex2f(v.x * LOG2E) + ex2f(v.y * LOG2E)
           + ex2f(v.z * LOG2E) + ex2f(v.w * LOG2E);
    }
    #pragma unroll
    for (int off = 16; off; off >>= 1)
        s += __shfl_xor_sync(0xffffffffu, s, off);

    __shared__ float sv[8];
    __shared__ float sLogZ2;
    int w = tid >> 5;
    if ((tid & 31) == 0) sv[w] = s;
    __syncthreads();
    if (tid == 0) {
        float Sv = sv[0];
        #pragma unroll
        for (int i = 1; i < 8; i++) Sv += sv[i];
        sLogZ2 = lg2f(Sv);
    }
    __syncthreads();

    if (tid < SS) {
        int lab = (tid & 1) ? __ldg(&targets[b*LL + (tid >> 1)]) : 0;
        g_lp[(size_t)row * SS + tid] = fmaf(rowp[lab], LOG2E, -sLogZ2);
    }
}

// ---------------------------------------------------------------------------
// K2: forward/backward quad scans. blocks [0,32) = forward (alpha, t=1..255),
//     blocks [32,64) = backward (beta', t=510..255). Independent SMs.
// ---------------------------------------------------------------------------
__global__ __launch_bounds__(32*SWARPS) void scan_kernel(const int* __restrict__ targets,
                                                         const int* __restrict__ act_lens,
                                                         const int* __restrict__ label_lens,
                                                         float* __restrict__ out) {
    const int tid = threadIdx.x;
    const int w   = tid >> 5;
    const int l   = tid & 31;

    __shared__ float bnd[2][SWARPS*MIR];

    if (blockIdx.x < BB) {
        // ================= FORWARD: alpha[255] =================
        const int b = blockIdx.x;
        const int s = OWN * w + l - MIR;          // mirrors for l<8
        const bool live = (s >= 0 && s < SS);
        const bool owned = (l >= MIR) && live;
        const int alen = act_lens[b];

        bool cs = false;
        if (live && (s & 1)) {
            int cl = targets[b*LL + (s >> 1)];
            int pl = (s >= 3) ? targets[b*LL + ((s - 2) >> 1)] : -1;
            cs = (cl != 0) && (cl != pl);
        }

        auto step = [&](float av, float lp, int t) -> float {
            float x2 = __shfl_up_sync(0xffffffffu, av, 1);
            float x3 = __shfl_up_sync(0xffffffffu, av, 2);
            float x3e = cs ? x3 : NEGF;
            float m = fmaxf(av, fmaxf(x2, x3e));
            float r = ex2f(av - m) + ex2f(x2 - m) + ex2f(x3e - m);
            float nv = m + lg2f(r) + lp;
            nv = (t < alen) ? nv : av;
            return live ? nv : NEGF;
        };

        float a = NEGF;
        if (live && s <= 1) a = g_lp[(size_t)b * SS + s];

        if (alen >= TT) {
            // tail lp: rows 253..255
            float lt0 = live ? g_lp[(size_t)(253*BB + b)*SS + s] : 0.f;
            float lt1 = live ? g_lp[(size_t)(254*BB + b)*SS + s] : 0.f;
            float lt2 = live ? g_lp[(size_t)(255*BB + b)*SS + s] : 0.f;

            float lqA[8], lqB[8];
            #pragma unroll
            for (int j = 0; j < 8; j++)
                lqA[j] = live ? g_lp[(size_t)((1 + j)*BB + b)*SS + s] : 0.f;
            __syncthreads();

            for (int q0 = 0; q0 < NQF; q0 += 2) {
                #pragma unroll
                for (int j = 0; j < 8; j++) {
                    int t = 1 + 4*(q0 + 2) + j;
                    bool ok = live && (t <= 252);
                    lqB[j] = ok ? g_lp[(size_t)(t*BB + b)*SS + s] : 0.f;
                }
                #pragma unroll
                for (int jq = 0; jq < 2; jq++) {
                    const int q = q0 + jq;
                    if (q >= NQF) break;          // uniform
                    const int t = 1 + 4*q;
                    float v1 = step(a,  lqA[4*jq + 0], t);
                    float v2 = step(v1, lqA[4*jq + 1], t + 1);
                    float v3 = step(v2, lqA[4*jq + 2], t + 2);
                    float v4 = step(v3, lqA[4*jq + 3], t + 3);
                    if (l >= 32 - MIR) bnd[jq][w*MIR + (l - (32 - MIR))] = v4;
                    __syncthreads();
                    if (l < MIR) a = (w > 0) ? bnd[jq][(w - 1)*MIR + l] : NEGF;
                    else         a = v4;
                }
                #pragma unroll
                for (int j = 0; j < 8; j++) lqA[j] = lqB[j];
            }
            // tail: 3 steps, mirrors fresh, erosion 6 <= 8 -> no barriers
            a = step(a, lt0, 253);
            a = step(a, lt1, 254);
            a = step(a, lt2, 255);

            if (owned) g_fa[b*SS + s] = a;
        } else {
            // fallback: generic full 512-step smem scan, result added here
            __shared__ float sal[2][SS];
            __shared__ float fin[SS];
            if (live) sal[0][s] = a;
            __syncthreads();
            int cur = 1;
            for (int t = 1; t < TT; t++) {
                if (live) {
                    float a1 = sal[cur^1][s];
                    float a2 = (s >= 1) ? sal[cur^1][s-1] : NEGF;
                    float a3 = (cs && s >= 2) ? sal[cur^1][s-2] : NEGF;
                    float mm = fmaxf(a1, fmaxf(a2, a3));
                    float r = ex2f(a1 - mm) + ex2f(a2 - mm) + ex2f(a3 - mm);
                    float nv = mm + lg2f(r) + g_lp[(size_t)(t*BB + b)*SS + s];
                    sal[cur][s] = (t < alen) ? nv : a1;
                }
                __syncthreads();
                cur ^= 1;
            }
            if (live) fin[s] = sal[cur^1][s];
            __syncthreads();
            if (tid == 0) {
                int sl = 2 * label_lens[b];
                float x = fin[sl], y = fin[sl - 1];
                float m = fmaxf(x, y);
                float ll2 = m + lg2f(ex2f(x - m) + ex2f(y - m));
                atomicAdd(out, -ll2 * (LN2 / (float)BB));
            }
        }
    } else {
        // ================= BACKWARD: beta'[255] =================
        const int b = blockIdx.x - BB;
        const int alen = act_lens[b];
        if (alen < TT) return;                    // fallback handled by forward

        const int s = OWN * w + l;                // lanes 0..23 owned, 24..31 mirror
        const bool live = (s < SS);
        const bool owned = (l < OWN) && live;

        // cs2 = can_skip INTO state s+2 (skip s -> s+2)
        bool cs2 = false;
        if (live && (s & 1) && (s + 2 < SS)) {
            int cl = targets[b*LL + ((s + 2) >> 1)];
            int pl = targets[b*LL + (s >> 1)];
            cs2 = (cl != 0) && (cl != pl);
        }

        auto stepb = [&](float av, float lpn) -> float {
            float u  = av + lpn;                  // beta'[t+1][s] + lp[t+1][s]
            float x1 = __shfl_down_sync(0xffffffffu, u, 1);
            float x2 = __shfl_down_sync(0xffffffffu, u, 2);
            float x2e = cs2 ? x2 : NEGF;
            float m = fmaxf(u, fmaxf(x1, x2e));
            float r = ex2f(u - m) + ex2f(x1 - m) + ex2f(x2e - m);
            float nv = m + lg2f(r);
            return live ? nv : NEGF;
        };

        // init at t=511
        int sl = 2 * label_lens[b];
        float a = (live && (s == sl || s == sl - 1)) ? 0.f : NEGF;

        // tail lp rows: steps t=258,257,256,255 use rows 259,258,257,256
        float lt0 = live ? g_lp[(size_t)(259*BB + b)*SS + s] : 0.f;
        float lt1 = live ? g_lp[(size_t)(258*BB + b)*SS + s] : 0.f;
        float lt2 = live ? g_lp[(size_t)(257*BB + b)*SS + s] : 0.f;
        float lt3 = live ? g_lp[(size_t)(256*BB + b)*SS + s] : 0.f;

        // main loop: quad q covers t = 510-4q .. 507-4q, using rows 511-4q-k
        float lqA[8], lqB[8];
        #pragma unroll
        for (int j = 0; j < 8; j++)
            lqA[j] = live ? g_lp[(size_t)((511 - j)*BB + b)*SS + s] : 0.f;
        __syncthreads();

        for (int q0 = 0; q0 < NQB; q0 += 2) {
            #pragma unroll
            for (int j = 0; j < 8; j++) {
                int rowi = 511 - 4*(q0 + 2) - j;
                bool ok = live && (rowi >= 260);
                lqB[j] = ok ? g_lp[(size_t)(rowi*BB + b)*SS + s] : 0.f;
            }
            #pragma unroll
            for (int jq = 0; jq < 2; jq++) {
                const int q = q0 + jq;
                if (q >= NQB) break;              // uniform
                float v1 = stepb(a,  lqA[4*jq + 0]);
                float v2 = stepb(v1, lqA[4*jq + 1]);
                float v3 = stepb(v2, lqA[4*jq + 2]);
                float v4 = stepb(v3, lqA[4*jq + 3]);
                // boundary: warp w+1's owned bottom 8 -> warp w's top mirrors
                if (l < MIR) bnd[jq][w*MIR + l] = v4;
                __syncthreads();
                if (l >= 32 - MIR)
                    a = (w < SWARPS - 1) ? bnd[jq][(w + 1)*MIR + (l - (32 - MIR))] : NEGF;
                else
                    a = v4;
            }
            #pragma unroll
            for (int j = 0; j < 8; j++) lqA[j] = lqB[j];
        }
        // tail: 4 steps, erosion 8 from top -> lanes 0..23 (owned) stay valid
        a = stepb(a, lt0);
        a = stepb(a, lt1);
        a = stepb(a, lt2);
        a = stepb(a, lt3);

        if (owned) g_fb[b*SS + s] = a;
    }
}

// ---------------------------------------------------------------------------
// K3: combine at t=255: ll = lse_s(alpha[255][s] + beta'[255][s]).
// ---------------------------------------------------------------------------
__global__ __launch_bounds__(256) void combine_kernel(const int* __restrict__ act_lens,
                                                      float* __restrict__ out) {
    const int b = blockIdx.x;
    if (act_lens[b] < TT) return;              // forward fallback already added
    const int tid = threadIdx.x;

    float v = NEGF;
    if (tid < SS) v = g_fa[b*SS + tid] + g_fb[b*SS + tid];

    // block lse reduce (max, then sum of exp2)
    float m = v;
    #pragma unroll
    for (int off = 16; off; off >>= 1)
        m = fmaxf(m, __shfl_xor_sync(0xffffffffu, m, off));
    __shared__ float sm[8], ssum[8];
    int w = tid >> 5;
    if ((tid & 31) == 0) sm[w] = m;
    __syncthreads();
    float M = sm[0];
    #pragma unroll
    for (int i = 1; i < 8; i++) M = fmaxf(M, sm[i]);

    float e = ex2f(v - M);
    #pragma unroll
    for (int off = 16; off; off >>= 1)
        e += __shfl_xor_sync(0xffffffffu, e, off);
    if ((tid & 31) == 0) ssum[w] = e;
    __syncthreads();
    if (tid == 0) {
        float Sv = ssum[0];
        #pragma unroll
        for (int i = 1; i < 8; i++) Sv += ssum[i];
        float ll2 = M + lg2f(Sv);
        atomicAdd(out, -ll2 * (LN2 / (float)BB));
    }
}

// ---------------------------------------------------------------------------
extern "C" void kernel_launch(void* const* d_in, const int* in_sizes, int n_in,
                              void* d_out, int out_size) {
    const float* acts       = (const float*)d_in[0];
    const int*   targets    = (const int*)d_in[1];
    const int*   act_lens   = (const int*)d_in[2];
    const int*   label_lens = (const int*)d_in[3];
    float* out = (float*)d_out;

    logz_gather_kernel<<<TT*BB, 256>>>(acts, targets, out);
    scan_kernel<<<2*BB, 32*SWARPS>>>(targets, act_lens, label_lens, out);
    combine_kernel<<<BB, 256>>>(act_lens, out);
}